// round 10
// baseline (speedup 1.0000x reference)
#include <cuda_runtime.h>
#include <cstdint>

// B=2, C=4, D=64, H=256, W=256; channels 1..3 of pred/trgt.
// scale(10)/(2*DELTA=10) cancels; vorticity linear -> stencil on (pred-trgt).
// keep voxel <=> min over 3^3 mask neighborhood == 1 (center included).
//
// Streaming design: 128 blocks (64 h-tiles x 2 batches), each walks d=1..62
// with a 4-slot cp.async SMEM ring. All stencil taps + mask come from SMEM.

constexpr int DN = 64, HN = 256, WN = 256;
constexpr long sD = (long)HN * WN;          // 65536
constexpr long sH = WN;                     // 256
constexpr long CS = (long)DN * HN * WN;     // 4194304
constexpr int HT = 4;                       // output h rows per block
constexpr int NHX = 64;                     // h tiles (h0 = 1 + 4*bx)
constexpr int NPART = NHX * 2;              // 128 blocks

// SMEM ring: per slot  u:6 rows, v:4 rows, w:6 rows (x pred,trgt), mask:6 rows
// floats: up 4*6*256, ut same, vp 4*4*256, vt, wp 4*6*256, wt, mk 4*6*256
constexpr int OF_UP = 0;
constexpr int OF_UT = OF_UP + 4 * 6 * 256;
constexpr int OF_VP = OF_UT + 4 * 6 * 256;
constexpr int OF_VT = OF_VP + 4 * 4 * 256;
constexpr int OF_WP = OF_VT + 4 * 4 * 256;
constexpr int OF_WT = OF_WP + 4 * 6 * 256;
constexpr int OF_MK = OF_WT + 4 * 6 * 256;
constexpr int SMEM_FLOATS = OF_MK + 4 * 6 * 256;   // 38912
constexpr int SMEM_BYTES  = SMEM_FLOATS * 4;       // 155648

constexpr int NROWS = 38;                   // rows fetched per plane
constexpr int NOPS  = (NROWS * 64 + 255) / 256;    // 10 cp.async per thread max

__device__ float2 g_part[NPART];
__device__ int g_counter;

__device__ __forceinline__ void cp16(uint32_t dst, const float* src) {
    asm volatile("cp.async.cg.shared.global [%0], [%1], 16;\n" :: "r"(dst), "l"(src));
}
__device__ __forceinline__ void cp_commit() {
    asm volatile("cp.async.commit_group;\n" ::: "memory");
}
__device__ __forceinline__ void cp_wait1() {
    asm volatile("cp.async.wait_group 1;\n" ::: "memory");
}
__device__ __forceinline__ float4 sub4(float4 a, float4 b) {
    return make_float4(a.x-b.x, a.y-b.y, a.z-b.z, a.w-b.w);
}
__device__ __forceinline__ float4 min4(float4 a, float4 b) {
    return make_float4(fminf(a.x,b.x), fminf(a.y,b.y), fminf(a.z,b.z), fminf(a.w,b.w));
}

// Grid: (NHX, 2)  block: 256 = 4 h-rows x 64 w-groups (float4 each).
__global__ __launch_bounds__(256) void vort_kernel(
    const float* __restrict__ pred,
    const float* __restrict__ trgt,
    const float* __restrict__ mask,
    float* __restrict__ out)
{
    extern __shared__ float sm[];
    const int tid = threadIdx.x;
    const int row = tid >> 6;                // 0..3
    const int w4  = (tid & 63) << 2;
    const int h0  = 1 + blockIdx.x * HT;
    const int h   = h0 + row;
    const int b   = blockIdx.y;

    // gmem channel bases (plane 0)
    const long gb = (long)b * 4 * CS;
    const float* gu_p = pred + gb + 1 * CS;
    const float* gv_p = pred + gb + 2 * CS;
    const float* gw_p = pred + gb + 3 * CS;
    const float* gu_t = trgt + gb + 1 * CS;
    const float* gv_t = trgt + gb + 2 * CS;
    const float* gw_t = trgt + gb + 3 * CS;
    const float* gm   = mask + (long)b * DN * sD;

    // ---- precompute this thread's fetch table (plane-invariant parts) ----
    const float* srcp[NOPS];     // plane-0 gmem address
    int dst_base[NOPS];          // smem float offset at slot 0
    int dst_str[NOPS];           // per-slot stride (rows*256)
    bool opok[NOPS];
    #pragma unroll
    for (int it = 0; it < NOPS; it++) {
        int i = tid + 256 * it;
        opok[it] = (i < NROWS * 64);
        int r  = i >> 6;
        int ln = (i & 63) << 2;
        const float* base; int off, rows, hh;
        if (r < 12)      { int rr = (r < 6) ? r : r - 6;
                           base = (r < 6) ? gu_p : gu_t; off = (r < 6) ? OF_UP : OF_UT;
                           rows = 6; hh = min(h0 - 1 + rr, HN - 1); off += rr * 256; }
        else if (r < 20) { int rr = (r - 12) & 3;
                           base = (r < 16) ? gv_p : gv_t; off = (r < 16) ? OF_VP : OF_VT;
                           rows = 4; hh = min(h0 + rr, HN - 1); off += rr * 256; }
        else if (r < 32) { int rr = (r - 20) < 6 ? (r - 20) : (r - 26);
                           base = (r < 26) ? gw_p : gw_t; off = (r < 26) ? OF_WP : OF_WT;
                           rows = 6; hh = min(h0 - 1 + rr, HN - 1); off += rr * 256; }
        else             { int rr = r - 32;
                           base = gm; off = OF_MK;
                           rows = 6; hh = min(h0 - 1 + rr, HN - 1); off += rr * 256; }
        srcp[it]     = base + (long)hh * sH + ln;
        dst_base[it] = off + ln;
        dst_str[it]  = rows * 256;
    }

    auto fetch = [&](int plane, int slot) {
        const long po = (long)plane * sD;
        #pragma unroll
        for (int it = 0; it < NOPS; it++) {
            if (opok[it]) {
                float* d = sm + dst_base[it] + slot * dst_str[it];
                cp16((uint32_t)__cvta_generic_to_shared(d), srcp[it] + po);
            }
        }
        cp_commit();
    };

    // ---- prologue: planes 0,1,2 into slots 0,1,2 ----
    fetch(0, 0);
    fetch(1, 1);
    fetch(2, 2);

    float numer = 0.0f, den = 0.0f;
    const bool hok = (h <= HN - 2);
    const int wlo = max(w4 - 1, 0);
    const int whi = min(w4 + 4, WN - 1);

    for (int d = 1; d <= 62; d++) {
        fetch(min(d + 2, DN - 1), (d + 2) & 3);
        cp_wait1();
        __syncthreads();

        if (hok) {
            const int s0 = (d - 1) & 3, s1 = d & 3, s2 = (d + 1) & 3;
            auto U = [&](int s, int r) { return *reinterpret_cast<const float4*>(sm + OF_UP + (s * 6 + r) * 256 + w4); };
            auto Ut= [&](int s, int r) { return *reinterpret_cast<const float4*>(sm + OF_UT + (s * 6 + r) * 256 + w4); };
            auto V = [&](int s, int r) { return *reinterpret_cast<const float4*>(sm + OF_VP + (s * 4 + r) * 256 + w4); };
            auto Vt= [&](int s, int r) { return *reinterpret_cast<const float4*>(sm + OF_VT + (s * 4 + r) * 256 + w4); };
            auto W = [&](int s, int r) { return *reinterpret_cast<const float4*>(sm + OF_WP + (s * 6 + r) * 256 + w4); };
            auto Wt= [&](int s, int r) { return *reinterpret_cast<const float4*>(sm + OF_WT + (s * 6 + r) * 256 + w4); };

            // derivatives (u rows store h0-1..h0+4 so center h -> row+1; v rows h0..h3 -> row)
            float4 du_d = sub4(sub4(U(s2,row+1), Ut(s2,row+1)), sub4(U(s0,row+1), Ut(s0,row+1)));
            float4 du_h = sub4(sub4(U(s1,row+2), Ut(s1,row+2)), sub4(U(s1,row  ), Ut(s1,row  )));
            float4 dv_d = sub4(sub4(V(s2,row  ), Vt(s2,row  )), sub4(V(s0,row  ), Vt(s0,row  )));
            float4 dw_h = sub4(sub4(W(s1,row+2), Wt(s1,row+2)), sub4(W(s1,row  ), Wt(s1,row  )));
            float4 vc   = sub4(V(s1,row), Vt(s1,row));
            float4 wc   = sub4(W(s1,row+1), Wt(s1,row+1));

            const float* vpr = sm + OF_VP + (s1 * 4 + row) * 256;
            const float* vtr = sm + OF_VT + (s1 * 4 + row) * 256;
            const float* wpr = sm + OF_WP + (s1 * 6 + row + 1) * 256;
            const float* wtr = sm + OF_WT + (s1 * 6 + row + 1) * 256;
            float vL = vpr[wlo] - vtr[wlo], vR = vpr[whi] - vtr[whi];
            float wL = wpr[wlo] - wtr[wlo], wR = wpr[whi] - wtr[whi];

            float4 dv_w = make_float4(vc.y - vL, vc.z - vc.x, vc.w - vc.y, vR - vc.z);
            float4 dw_w = make_float4(wc.y - wL, wc.z - wc.x, wc.w - wc.y, wR - wc.z);

            float4 vx = sub4(dw_h, dv_d);
            float4 vy = sub4(du_d, dw_w);
            float4 vz = sub4(dv_w, du_h);

            // mask 3^3 min: rows row..row+2 of the 6-row window, planes s0..s2
            float4 cm = make_float4(1e9f, 1e9f, 1e9f, 1e9f);
            float cmL = 1e9f, cmR = 1e9f;
            #pragma unroll
            for (int y = 0; y < 3; y++) {
                const float* m0 = sm + OF_MK + (s0 * 6 + row + y) * 256;
                const float* m1 = sm + OF_MK + (s1 * 6 + row + y) * 256;
                const float* m2 = sm + OF_MK + (s2 * 6 + row + y) * 256;
                float4 q = min4(*reinterpret_cast<const float4*>(m0 + w4),
                           min4(*reinterpret_cast<const float4*>(m1 + w4),
                                *reinterpret_cast<const float4*>(m2 + w4)));
                cm  = min4(cm, q);
                cmL = fminf(cmL, fminf(m0[wlo], fminf(m1[wlo], m2[wlo])));
                cmR = fminf(cmR, fminf(m0[whi], fminf(m1[whi], m2[whi])));
            }
            float k0 = fminf(cmL,  fminf(cm.x, cm.y));
            float k1 = fminf(cm.x, fminf(cm.y, cm.z));
            float k2 = fminf(cm.y, fminf(cm.z, cm.w));
            float k3 = fminf(cm.z, fminf(cm.w, cmR));
            if (w4 > 0 && k0 > 0.5f)      { numer += sqrtf(vx.x*vx.x + vy.x*vy.x + vz.x*vz.x); den += 1.0f; }
            if (k1 > 0.5f)                { numer += sqrtf(vx.y*vx.y + vy.y*vy.y + vz.y*vz.y); den += 1.0f; }
            if (k2 > 0.5f)                { numer += sqrtf(vx.z*vx.z + vy.z*vy.z + vz.z*vz.z); den += 1.0f; }
            if (w4 < WN - 4 && k3 > 0.5f) { numer += sqrtf(vx.w*vx.w + vy.w*vy.w + vz.w*vz.w); den += 1.0f; }
        }
        __syncthreads();   // protect ring slots before next fetch overwrites
    }

    // ---- block reduction (8 warps) ----
    const int lane = tid & 31, wid = tid >> 5;
    #pragma unroll
    for (int s = 16; s; s >>= 1) {
        numer += __shfl_down_sync(0xffffffffu, numer, s);
        den   += __shfl_down_sync(0xffffffffu, den,   s);
    }
    __shared__ float wn[8], wd[8];
    __shared__ bool isLast;
    if (lane == 0) { wn[wid] = numer; wd[wid] = den; }
    __syncthreads();
    if (wid == 0) {
        float n2 = (lane < 8) ? wn[lane] : 0.0f;
        float d2 = (lane < 8) ? wd[lane] : 0.0f;
        #pragma unroll
        for (int s = 4; s; s >>= 1) {
            n2 += __shfl_down_sync(0xffffffffu, n2, s);
            d2 += __shfl_down_sync(0xffffffffu, d2, s);
        }
        if (lane == 0) {
            const int bid = blockIdx.x + NHX * blockIdx.y;
            g_part[bid] = make_float2(n2, d2);
            __threadfence();
            int prev = atomicAdd(&g_counter, 1);
            isLast = (prev == NPART - 1);
        }
    }
    __syncthreads();

    if (isLast) {
        __threadfence();
        double n = 0.0, dd = 0.0;
        for (int i = tid; i < NPART; i += 256) {
            float2 p = g_part[i];
            n += (double)p.x; dd += (double)p.y;
        }
        #pragma unroll
        for (int s = 16; s; s >>= 1) {
            n  += __shfl_down_sync(0xffffffffu, n,  s);
            dd += __shfl_down_sync(0xffffffffu, dd, s);
        }
        __shared__ double sn[8], sd[8];
        if (lane == 0) { sn[wid] = n; sd[wid] = dd; }
        __syncthreads();
        if (wid == 0) {
            n  = (lane < 8) ? sn[lane] : 0.0;
            dd = (lane < 8) ? sd[lane] : 0.0;
            #pragma unroll
            for (int s = 4; s; s >>= 1) {
                n  += __shfl_down_sync(0xffffffffu, n,  s);
                dd += __shfl_down_sync(0xffffffffu, dd, s);
            }
            if (lane == 0) {
                out[0] = (float)(n / dd);
                g_counter = 0;
            }
        }
    }
}

extern "C" void kernel_launch(void* const* d_in, const int* in_sizes, int n_in,
                              void* d_out, int out_size) {
    const float* pred = (const float*)d_in[0];   // predicts (2,4,64,256,256)
    const float* trgt = (const float*)d_in[1];   // targets  (2,4,64,256,256)
    const float* mask = (const float*)d_in[2];   // masks    (2,1,64,256,256)
    float* out = (float*)d_out;

    cudaFuncSetAttribute(vort_kernel,
                         cudaFuncAttributeMaxDynamicSharedMemorySize, SMEM_BYTES);
    dim3 grid(NHX, 2);
    vort_kernel<<<grid, 256, SMEM_BYTES>>>(pred, trgt, mask, out);
}

// round 11
// speedup vs baseline: 1.5522x; 1.5522x over previous
#include <cuda_runtime.h>

// B=2, C=4, D=64, H=256, W=256; channels 1..3 of pred/trgt.
// scale(10)/(2*DELTA=10) cancels; vorticity linear -> stencil on (pred-trgt).
// keep voxel <=> min over 3^3 mask neighborhood == 1 (center included).
// Conditional stencil: only ~30% of threads (those with a kept voxel among
// their 4) issue the 18 f4 stencil loads -> ~2x fewer DRAM sectors.

constexpr int DN = 64, HN = 256, WN = 256;
constexpr long sD = (long)HN * WN;          // 65536
constexpr long sH = WN;                     // 256
constexpr long CS = (long)DN * HN * WN;     // 4194304
constexpr int HT = 4;                       // h rows per block
constexpr int NHX = 64;                     // ceil(254/4)
constexpr int NPART = NHX * 62 * 2;         // 7936 blocks

__device__ float2 g_part[NPART];
__device__ int g_counter;                   // zero-init; self-resets each launch

__device__ __forceinline__ float4 ld4(const float* p) {
    return __ldg(reinterpret_cast<const float4*>(p));
}
__device__ __forceinline__ float4 min4(float4 a, float4 b) {
    return make_float4(fminf(a.x,b.x), fminf(a.y,b.y), fminf(a.z,b.z), fminf(a.w,b.w));
}
__device__ __forceinline__ float4 sub4(float4 a, float4 b) {
    return make_float4(a.x-b.x, a.y-b.y, a.z-b.z, a.w-b.w);
}
// (p[+off]-t[+off]) - (p[-off]-t[-off])
__device__ __forceinline__ float4 dd4(const float* p, const float* t, long off) {
    return sub4(sub4(ld4(p + off), ld4(t + off)), sub4(ld4(p - off), ld4(t - off)));
}

// Grid: (NHX, 62, 2)  block: 256 = 4 h-rows x 64 w-threads (float4 each).
__global__ __launch_bounds__(256) void vort_kernel(
    const float* __restrict__ pred,
    const float* __restrict__ trgt,
    const float* __restrict__ mask,
    float* __restrict__ out)
{
    const int tid  = threadIdx.x;
    const int row  = tid >> 6;               // 0..3
    const int t    = tid & 63;               // w-group
    const int lane = tid & 31;
    const int w4   = t << 2;                 // first w of this thread
    const int h    = 1 + blockIdx.x * HT + row;
    const int hc   = min(h, HN - 2);         // clamp; h>254 discarded later
    const int d    = 1 + blockIdx.y;         // 1..62
    const int b    = blockIdx.z;

    // ---- mask: per-w min over 3x3 (dz,dy) at this thread's 4 w ----
    const float* mb = mask + (long)b * DN * sD + (long)d * sD + (long)hc * sH + w4;
    float4 cm = make_float4(1e9f, 1e9f, 1e9f, 1e9f);
    #pragma unroll
    for (int dz = -1; dz <= 1; dz++)
        #pragma unroll
        for (int dy = -1; dy <= 1; dy++)
            cm = min4(cm, ld4(mb + (long)dz * sD + (long)dy * sH));

    __shared__ float cs[HT][WN];
    *reinterpret_cast<float4*>(&cs[row][w4]) = cm;
    __syncthreads();

    // w-direction min for keep flags
    const float cmL = cs[row][max(w4 - 1, 0)];
    const float cmR = cs[row][min(w4 + 4, WN - 1)];
    const bool hok = (h <= HN - 2);
    const bool k0 = hok && (w4 > 0)      && fminf(cmL,  fminf(cm.x, cm.y)) > 0.5f;
    const bool k1 = hok &&                  fminf(cm.x, fminf(cm.y, cm.z)) > 0.5f;
    const bool k2 = hok &&                  fminf(cm.y, fminf(cm.z, cm.w)) > 0.5f;
    const bool k3 = hok && (w4 < WN - 4) && fminf(cm.z, fminf(cm.w, cmR)) > 0.5f;

    float numer = 0.0f;
    float den   = 0.0f;

    if (k0 | k1 | k2 | k3) {
        // ---- stencil on (pred - trgt), only for threads with a kept voxel ----
        const long pb = (long)b * 4 * CS + (long)d * sD + (long)hc * sH + w4;
        const float* pu = pred + pb + 1 * CS;
        const float* pv = pred + pb + 2 * CS;
        const float* pw = pred + pb + 3 * CS;
        const float* tu = trgt + pb + 1 * CS;
        const float* tv = trgt + pb + 2 * CS;
        const float* tw = trgt + pb + 3 * CS;

        float4 du_d = dd4(pu, tu, sD);       // du/dD
        float4 du_h = dd4(pu, tu, sH);       // du/dH
        float4 dv_d = dd4(pv, tv, sD);       // dv/dD
        float4 dw_h = dd4(pw, tw, sH);       // dw/dH
        float4 vc   = sub4(ld4(pv), ld4(tv));
        float4 wc   = sub4(ld4(pw), ld4(tw));

        const long eL = (w4 > 0)      ? -1 : 0;   // clamped; comp discarded at edge
        const long eR = (w4 < WN - 4) ?  4 : 3;
        float vL = __ldg(pv + eL) - __ldg(tv + eL);
        float vR = __ldg(pv + eR) - __ldg(tv + eR);
        float wL = __ldg(pw + eL) - __ldg(tw + eL);
        float wR = __ldg(pw + eR) - __ldg(tw + eR);

        float4 dv_w = make_float4(vc.y - vL, vc.z - vc.x, vc.w - vc.y, vR - vc.z);
        float4 dw_w = make_float4(wc.y - wL, wc.z - wc.x, wc.w - wc.y, wR - wc.z);

        // vor_x = dw/dH - dv/dD ; vor_y = du/dD - dw/dW ; vor_z = dv/dW - du/dH
        float4 vx = sub4(dw_h, dv_d);
        float4 vy = sub4(du_d, dw_w);
        float4 vz = sub4(dv_w, du_h);

        if (k0) { numer += sqrtf(vx.x*vx.x + vy.x*vy.x + vz.x*vz.x); den += 1.0f; }
        if (k1) { numer += sqrtf(vx.y*vx.y + vy.y*vy.y + vz.y*vz.y); den += 1.0f; }
        if (k2) { numer += sqrtf(vx.z*vx.z + vy.z*vy.z + vz.z*vz.z); den += 1.0f; }
        if (k3) { numer += sqrtf(vx.w*vx.w + vy.w*vy.w + vz.w*vz.w); den += 1.0f; }
    }

    // ---- block reduction (8 warps) ----
    #pragma unroll
    for (int s = 16; s; s >>= 1) {
        numer += __shfl_down_sync(0xffffffffu, numer, s);
        den   += __shfl_down_sync(0xffffffffu, den,   s);
    }
    __shared__ float wn[8], wd[8];
    const int wid = tid >> 5;
    if (lane == 0) { wn[wid] = numer; wd[wid] = den; }
    __syncthreads();

    __shared__ bool isLast;
    if (wid == 0) {
        float n2 = (lane < 8) ? wn[lane] : 0.0f;
        float d2 = (lane < 8) ? wd[lane] : 0.0f;
        #pragma unroll
        for (int s = 4; s; s >>= 1) {
            n2 += __shfl_down_sync(0xffffffffu, n2, s);
            d2 += __shfl_down_sync(0xffffffffu, d2, s);
        }
        if (lane == 0) {
            const int bid = blockIdx.x + NHX * (blockIdx.y + 62 * blockIdx.z);
            g_part[bid] = make_float2(n2, d2);
            __threadfence();
            int prev = atomicAdd(&g_counter, 1);
            isLast = (prev == NPART - 1);
        }
    }
    __syncthreads();

    // ---- last block finalizes (no tail kernel) ----
    if (isLast) {
        __threadfence();
        double n = 0.0, dd = 0.0;
        for (int i = tid; i < NPART; i += 256) {
            float2 p = g_part[i];
            n  += (double)p.x;
            dd += (double)p.y;
        }
        #pragma unroll
        for (int s = 16; s; s >>= 1) {
            n  += __shfl_down_sync(0xffffffffu, n,  s);
            dd += __shfl_down_sync(0xffffffffu, dd, s);
        }
        __shared__ double sn[8], sd[8];
        if (lane == 0) { sn[wid] = n; sd[wid] = dd; }
        __syncthreads();
        if (wid == 0) {
            n  = (lane < 8) ? sn[lane] : 0.0;
            dd = (lane < 8) ? sd[lane] : 0.0;
            #pragma unroll
            for (int s = 4; s; s >>= 1) {
                n  += __shfl_down_sync(0xffffffffu, n,  s);
                dd += __shfl_down_sync(0xffffffffu, dd, s);
            }
            if (lane == 0) {
                out[0] = (float)(n / dd);
                g_counter = 0;              // reset for next graph replay
            }
        }
    }
}

extern "C" void kernel_launch(void* const* d_in, const int* in_sizes, int n_in,
                              void* d_out, int out_size) {
    const float* pred = (const float*)d_in[0];   // predicts (2,4,64,256,256)
    const float* trgt = (const float*)d_in[1];   // targets  (2,4,64,256,256)
    const float* mask = (const float*)d_in[2];   // masks    (2,1,64,256,256)
    float* out = (float*)d_out;

    dim3 grid(NHX, 62, 2);
    vort_kernel<<<grid, 256>>>(pred, trgt, mask, out);
}